// round 3
// baseline (speedup 1.0000x reference)
#include <cuda_runtime.h>
#include <cstdint>

#define NMAX 100000
#define EMAX 1600000
#define HID  64
#define INCH 128

// ---------------- scratch (static device globals; no allocation) ----------------
__device__ __align__(256) float g_P[(size_t)NMAX * HID];   // h @ w_rel
__device__ __align__(256) float g_B[(size_t)NMAX * HID];   // h @ w_root + b_rel
__device__ __align__(256) float g_H[(size_t)NMAX * HID];   // activations
__device__ int   g_src[EMAX];
__device__ int   g_dstA[EMAX];
__device__ int   g_col[EMAX];          // CSR column (src) array
__device__ int   g_deg[NMAX];
__device__ int   g_rowptr[NMAX + 1];
__device__ int   g_cursor[NMAX];
__device__ int   g_batch[NMAX];
__device__ int   g_bsum[256];
__device__ int   g_boff[256];
__device__ float g_gsum[64 * HID];
__device__ int   g_gcnt[64];
__device__ int   g_flag64;             // 1 if edge_index/batch stored as int64

// ---------------- dtype detection ----------------
__global__ void k_detect(const int* e32) {
    __shared__ int any;
    if (threadIdx.x == 0) any = 0;
    __syncthreads();
    int v = 0;
    // If data is int64, every odd 32-bit word (high half) is 0 (values < 1e5).
    // If data is int32, odd words are random src indices — nonzero w.h.p.
    for (int i = threadIdx.x; i < 1024; i += blockDim.x) v |= e32[2 * i + 1];
    if (v) atomicOr(&any, 1);
    __syncthreads();
    if (threadIdx.x == 0) g_flag64 = (any == 0) ? 1 : 0;
}

// ---------------- zero scratch that accumulates ----------------
__global__ void k_zero(int n) {
    int i = blockIdx.x * blockDim.x + threadIdx.x;
    if (i < n) g_deg[i] = 0;
    if (i < 64 * HID) g_gsum[i] = 0.f;
}

// ---------------- index conversion + degree histogram ----------------
__global__ void k_convert_edges(const void* eraw, int e) {
    int i = blockIdx.x * blockDim.x + threadIdx.x;
    if (i >= e) return;
    int s, d;
    if (g_flag64) {
        const long long* p = (const long long*)eraw;
        s = (int)p[i];
        d = (int)p[(size_t)e + i];
    } else {
        const int* p = (const int*)eraw;
        s = p[i];
        d = p[e + i];
    }
    g_src[i] = s;
    g_dstA[i] = d;
    atomicAdd(&g_deg[d], 1);
}

__global__ void k_convert_batch(const void* braw, int n) {
    int i = blockIdx.x * blockDim.x + threadIdx.x;
    if (i >= n) return;
    g_batch[i] = g_flag64 ? (int)((const long long*)braw)[i] : ((const int*)braw)[i];
}

// ---------------- 3-kernel exclusive scan over degrees ----------------
__global__ void k_scan1(int n) {
    __shared__ int s[1024];
    int i = blockIdx.x * 1024 + threadIdx.x;
    int v = (i < n) ? g_deg[i] : 0;
    s[threadIdx.x] = v;
    __syncthreads();
#pragma unroll
    for (int off = 1; off < 1024; off <<= 1) {
        int t = (threadIdx.x >= (unsigned)off) ? s[threadIdx.x - off] : 0;
        __syncthreads();
        s[threadIdx.x] += t;
        __syncthreads();
    }
    if (i < n) g_rowptr[i] = s[threadIdx.x] - v;   // exclusive within block
    if (threadIdx.x == 1023) g_bsum[blockIdx.x] = s[1023];
}

__global__ void k_scan2(int nb) {
    if (threadIdx.x == 0 && blockIdx.x == 0) {
        int run = 0;
        for (int b = 0; b < nb; b++) { int t = g_bsum[b]; g_boff[b] = run; run += t; }
    }
}

__global__ void k_scan3(int n, int e) {
    int i = blockIdx.x * 1024 + threadIdx.x;
    if (i < n) {
        int v = g_rowptr[i] + g_boff[blockIdx.x];
        g_rowptr[i] = v;
        g_cursor[i] = v;
    }
    if (i == 0) g_rowptr[n] = e;
}

__global__ void k_fill(int e) {
    int i = blockIdx.x * blockDim.x + threadIdx.x;
    if (i >= e) return;
    int d = g_dstA[i];
    int pos = atomicAdd(&g_cursor[d], 1);
    g_col[pos] = g_src[i];
}

// ---------------- dual GEMM: P = X @ Wrel ; B = X @ Wroot + b_rel ----------------
// Block: 256 threads, 64-row tile, each thread computes 4 rows x (4 P-cols + 4 B-cols).
template <int K>
__global__ __launch_bounds__(256) void k_gemm_dual(
    const float* __restrict__ X,
    const float* __restrict__ Wrel,
    const float* __restrict__ Wroot,
    const float* __restrict__ brel,
    int n)
{
    extern __shared__ float sm[];
    float* Ws = sm;                // [K][128]: cols 0-63 = Wrel, 64-127 = Wroot
    float* Hs = sm + K * 128;      // [64][K]
    const float* src = (K == INCH) ? X : g_H;

    int tid = threadIdx.x;
    int row0 = blockIdx.x * 64;

    for (int i = tid; i < K * 64; i += 256) {
        int k = i >> 6, c = i & 63;
        Ws[k * 128 + c]      = Wrel[i];
        Ws[k * 128 + 64 + c] = Wroot[i];
    }
    for (int i = tid; i < (64 * K) / 4; i += 256) {
        int el = i * 4;
        int r = el / K, kk = el % K;
        int gr = row0 + r;
        float4 v = make_float4(0.f, 0.f, 0.f, 0.f);
        if (gr < n) v = *(const float4*)(src + (size_t)gr * K + kk);
        *(float4*)(Hs + r * K + kk) = v;
    }
    __syncthreads();

    int tx = tid & 15, ty = tid >> 4;
    int c0 = tx * 4;          // 4 contiguous cols in each half (conflict-free LDS.128)
    int r0 = ty * 4;

    float acc[4][8];
#pragma unroll
    for (int i = 0; i < 4; i++)
#pragma unroll
        for (int j = 0; j < 8; j++) acc[i][j] = 0.f;

#pragma unroll 8
    for (int k = 0; k < K; k++) {
        float a0 = Hs[(r0 + 0) * K + k];
        float a1 = Hs[(r0 + 1) * K + k];
        float a2 = Hs[(r0 + 2) * K + k];
        float a3 = Hs[(r0 + 3) * K + k];
        float4 b0 = *(float4*)&Ws[k * 128 + c0];        // Wrel cols
        float4 b1 = *(float4*)&Ws[k * 128 + 64 + c0];   // Wroot cols
        float b[8] = {b0.x, b0.y, b0.z, b0.w, b1.x, b1.y, b1.z, b1.w};
#pragma unroll
        for (int j = 0; j < 8; j++) {
            acc[0][j] = fmaf(a0, b[j], acc[0][j]);
            acc[1][j] = fmaf(a1, b[j], acc[1][j]);
            acc[2][j] = fmaf(a2, b[j], acc[2][j]);
            acc[3][j] = fmaf(a3, b[j], acc[3][j]);
        }
    }

    float bb0 = brel[c0 + 0], bb1 = brel[c0 + 1], bb2 = brel[c0 + 2], bb3 = brel[c0 + 3];
#pragma unroll
    for (int i = 0; i < 4; i++) {
        int gr = row0 + r0 + i;
        if (gr >= n) continue;
        *(float4*)(g_P + (size_t)gr * 64 + c0) =
            make_float4(acc[i][0], acc[i][1], acc[i][2], acc[i][3]);
        *(float4*)(g_B + (size_t)gr * 64 + c0) =
            make_float4(acc[i][4] + bb0, acc[i][5] + bb1, acc[i][6] + bb2, acc[i][7] + bb3);
    }
}

// ---------------- pull aggregation: H[i] = relu(B[i] + sum_{j in N(i)} P[j]) ----------------
// 16 threads per node, float4 per thread. P (25.6MB) is L2-resident.
__global__ __launch_bounds__(256) void k_agg(int n) {
    int t = blockIdx.x * blockDim.x + threadIdx.x;
    int gid = t >> 4;
    int l4 = (t & 15) * 4;
    if (gid >= n) return;
    int beg = g_rowptr[gid], end = g_rowptr[gid + 1];
    float4 acc = *(const float4*)(g_B + (size_t)gid * 64 + l4);
    int j = beg;
    for (; j + 3 < end; j += 4) {
        int s0 = g_col[j], s1 = g_col[j + 1], s2 = g_col[j + 2], s3 = g_col[j + 3];
        float4 v0 = *(const float4*)(g_P + (size_t)s0 * 64 + l4);
        float4 v1 = *(const float4*)(g_P + (size_t)s1 * 64 + l4);
        float4 v2 = *(const float4*)(g_P + (size_t)s2 * 64 + l4);
        float4 v3 = *(const float4*)(g_P + (size_t)s3 * 64 + l4);
        acc.x += (v0.x + v1.x) + (v2.x + v3.x);
        acc.y += (v0.y + v1.y) + (v2.y + v3.y);
        acc.z += (v0.z + v1.z) + (v2.z + v3.z);
        acc.w += (v0.w + v1.w) + (v2.w + v3.w);
    }
    for (; j < end; j++) {
        int s = g_col[j];
        float4 v = *(const float4*)(g_P + (size_t)s * 64 + l4);
        acc.x += v.x; acc.y += v.y; acc.z += v.z; acc.w += v.w;
    }
    acc.x = fmaxf(acc.x, 0.f);
    acc.y = fmaxf(acc.y, 0.f);
    acc.z = fmaxf(acc.z, 0.f);
    acc.w = fmaxf(acc.w, 0.f);
    *(float4*)(g_H + (size_t)gid * 64 + l4) = acc;
}

// ---------------- pooling: run-length accumulate (batch is sorted), few atomics ----------------
__global__ __launch_bounds__(256) void k_pool(int n) {
    int d = threadIdx.x & 63;
    int s = threadIdx.x >> 6;      // 0..3
    int start = blockIdx.x * 1024;
    int endn = min(start + 1024, n);
    float acc = 0.f;
    int curg = -1;
    for (int node = start + s; node < endn; node += 4) {
        int g = g_batch[node];
        if (g != curg) {
            if (curg >= 0) atomicAdd(&g_gsum[curg * 64 + d], acc);
            acc = 0.f; curg = g;
        }
        acc += g_H[(size_t)node * 64 + d];
    }
    if (curg >= 0) atomicAdd(&g_gsum[curg * 64 + d], acc);
}

__global__ void k_count(int n) {
    int g = threadIdx.x;           // 64 threads
    if (g >= 64) return;
    int lo0 = 0, hi = n;
    while (lo0 < hi) { int m = (lo0 + hi) >> 1; if (g_batch[m] < g) lo0 = m + 1; else hi = m; }
    int lo1 = lo0; hi = n;
    while (lo1 < hi) { int m = (lo1 + hi) >> 1; if (g_batch[m] < g + 1) lo1 = m + 1; else hi = m; }
    g_gcnt[g] = lo1 - lo0;
}

// ---------------- MLP head ----------------
__global__ __launch_bounds__(256) void k_head(
    const float* __restrict__ W1, const float* __restrict__ b1,
    const float* __restrict__ W2, const float* __restrict__ b2,
    float* __restrict__ out)
{
    __shared__ float pm[64 * 64];
    __shared__ float w1s[64 * 64];
    __shared__ float z[64 * 64];
    int tid = threadIdx.x;
    for (int i = tid; i < 4096; i += 256) {
        int g = i >> 6;
        pm[i] = g_gsum[i] / fmaxf((float)g_gcnt[g], 1.f);
        w1s[i] = W1[i];
    }
    __syncthreads();
    for (int idx = tid; idx < 4096; idx += 256) {
        int g = idx >> 6, jj = idx & 63;
        float s = b1[jj];
#pragma unroll 8
        for (int k = 0; k < 64; k++) s = fmaf(pm[g * 64 + k], w1s[k * 64 + jj], s);
        z[idx] = fmaxf(s, 0.f);
    }
    __syncthreads();
    if (tid < 128) {
        int g = tid >> 1, o = tid & 1;
        float s = b2[o];
#pragma unroll 8
        for (int jj = 0; jj < 64; jj++) s = fmaf(z[g * 64 + jj], W2[jj * 2 + o], s);
        out[g * 2 + o] = s;
    }
}

// ---------------- launch ----------------
extern "C" void kernel_launch(void* const* d_in, const int* in_sizes, int n_in,
                              void* d_out, int out_size)
{
    const float* x      = (const float*)d_in[0];
    const void*  eidx   = d_in[1];
    const void*  batch  = d_in[2];
    const float* wr0    = (const float*)d_in[3];
    const float* br0    = (const float*)d_in[4];
    const float* wroot0 = (const float*)d_in[5];
    const float* wr1    = (const float*)d_in[6];
    const float* br1    = (const float*)d_in[7];
    const float* wroot1 = (const float*)d_in[8];
    const float* wr2    = (const float*)d_in[9];
    const float* br2    = (const float*)d_in[10];
    const float* wroot2 = (const float*)d_in[11];
    const float* hw1    = (const float*)d_in[12];
    const float* hb1    = (const float*)d_in[13];
    const float* hw2    = (const float*)d_in[14];
    const float* hb2    = (const float*)d_in[15];

    int n = in_sizes[0] / INCH;    // 100000
    int e = in_sizes[1] / 2;       // 1600000 (element count is dtype-independent)

    cudaFuncSetAttribute(k_gemm_dual<INCH>, cudaFuncAttributeMaxDynamicSharedMemorySize,
                         INCH * 192 * 4);
    cudaFuncSetAttribute(k_gemm_dual<HID>, cudaFuncAttributeMaxDynamicSharedMemorySize,
                         HID * 192 * 4);

    k_detect<<<1, 256>>>((const int*)eidx);
    k_zero<<<(n + 255) / 256, 256>>>(n);
    k_convert_edges<<<(e + 255) / 256, 256>>>(eidx, e);
    k_convert_batch<<<(n + 255) / 256, 256>>>(batch, n);

    int nb = (n + 1023) / 1024;
    k_scan1<<<nb, 1024>>>(n);
    k_scan2<<<1, 32>>>(nb);
    k_scan3<<<nb, 1024>>>(n, e);
    k_fill<<<(e + 255) / 256, 256>>>(e);

    int gb = (n + 63) / 64;
    int ab = ((n * 16) + 255) / 256;

    // Layer 0 (K=128 input)
    k_gemm_dual<INCH><<<gb, 256, INCH * 192 * 4>>>(x, wr0, wroot0, br0, n);
    k_agg<<<ab, 256>>>(n);
    // Layer 1
    k_gemm_dual<HID><<<gb, 256, HID * 192 * 4>>>(nullptr, wr1, wroot1, br1, n);
    k_agg<<<ab, 256>>>(n);
    // Layer 2
    k_gemm_dual<HID><<<gb, 256, HID * 192 * 4>>>(nullptr, wr2, wroot2, br2, n);
    k_agg<<<ab, 256>>>(n);

    k_pool<<<(n + 1023) / 1024, 256>>>(n);
    k_count<<<1, 64>>>(n);
    k_head<<<1, 256>>>(hw1, hb1, hw2, hb2, (float*)d_out);
}

// round 7
// speedup vs baseline: 1.0704x; 1.0704x over previous
#include <cuda_runtime.h>
#include <cstdint>

#define NMAX 100000
#define EMAX 1600000
#define HID  64
#define INCH 128

// ---------------- scratch (static device globals; no allocation) ----------------
__device__ __align__(256) float g_P[(size_t)NMAX * HID];   // h @ w_rel
__device__ __align__(256) float g_B[(size_t)NMAX * HID];   // h @ w_root + b_rel
__device__ __align__(256) float g_H[(size_t)NMAX * HID];   // activations
__device__ int   g_col[EMAX];          // CSR column (src) array
__device__ int   g_deg[NMAX];
__device__ int   g_rowptr[NMAX + 1];
__device__ int   g_cursor[NMAX];
__device__ int   g_batch[NMAX];
__device__ int   g_bsum[256];
__device__ int   g_boff[256];
__device__ float g_gsum[64 * HID];
__device__ int   g_gcnt[64];
__device__ int   g_flag64;             // 1 if edge_index/batch stored as int64

// ---------------- f32x2 packed-FMA helpers (ptxas never emits FFMA2 from C++) ----
__device__ __forceinline__ unsigned long long pack2(float lo, float hi) {
    unsigned long long r;
    asm("mov.b64 %0, {%1, %2};" : "=l"(r) : "f"(lo), "f"(hi));
    return r;
}
__device__ __forceinline__ void ffma2(unsigned long long& d,
                                      unsigned long long a, unsigned long long b) {
    asm("fma.rn.f32x2 %0, %1, %2, %0;" : "+l"(d) : "l"(a), "l"(b));
}
__device__ __forceinline__ void unpack2(unsigned long long v, float& lo, float& hi) {
    asm("mov.b64 {%0, %1}, %2;" : "=f"(lo), "=f"(hi) : "l"(v));
}

// ---------------- dtype detection ----------------
__global__ void k_detect(const int* e32) {
    __shared__ int any;
    if (threadIdx.x == 0) any = 0;
    __syncthreads();
    int v = 0;
    // int64: every odd 32-bit word (high half) is 0 (values < 1e5).
    // int32: odd words are random node indices — nonzero w.h.p.
    for (int i = threadIdx.x; i < 1024; i += blockDim.x) v |= e32[2 * i + 1];
    if (v) atomicOr(&any, 1);
    __syncthreads();
    if (threadIdx.x == 0) g_flag64 = (any == 0) ? 1 : 0;
}

// ---------------- zero scratch that accumulates ----------------
__global__ void k_zero(int n) {
    int i = blockIdx.x * blockDim.x + threadIdx.x;
    if (i < n) g_deg[i] = 0;
    if (i < 64 * HID) g_gsum[i] = 0.f;
}

// ---------------- degree histogram straight from raw input ----------------
__global__ void k_hist(const void* eraw, int e) {
    int i = blockIdx.x * blockDim.x + threadIdx.x;
    if (i >= e) return;
    int d = g_flag64 ? (int)((const long long*)eraw)[(size_t)e + i]
                     : ((const int*)eraw)[e + i];
    atomicAdd(&g_deg[d], 1);
}

__global__ void k_convert_batch(const void* braw, int n) {
    int i = blockIdx.x * blockDim.x + threadIdx.x;
    if (i >= n) return;
    g_batch[i] = g_flag64 ? (int)((const long long*)braw)[i] : ((const int*)braw)[i];
}

// ---------------- 3-kernel exclusive scan over degrees ----------------
__global__ void k_scan1(int n) {
    __shared__ int s[1024];
    int i = blockIdx.x * 1024 + threadIdx.x;
    int v = (i < n) ? g_deg[i] : 0;
    s[threadIdx.x] = v;
    __syncthreads();
#pragma unroll
    for (int off = 1; off < 1024; off <<= 1) {
        int t = (threadIdx.x >= (unsigned)off) ? s[threadIdx.x - off] : 0;
        __syncthreads();
        s[threadIdx.x] += t;
        __syncthreads();
    }
    if (i < n) g_rowptr[i] = s[threadIdx.x] - v;   // exclusive within block
    if (threadIdx.x == 1023) g_bsum[blockIdx.x] = s[1023];
}

__global__ void k_scan2(int nb) {
    if (threadIdx.x == 0 && blockIdx.x == 0) {
        int run = 0;
        for (int b = 0; b < nb; b++) { int t = g_bsum[b]; g_boff[b] = run; run += t; }
    }
}

__global__ void k_scan3(int n, int e) {
    int i = blockIdx.x * 1024 + threadIdx.x;
    if (i < n) {
        int v = g_rowptr[i] + g_boff[blockIdx.x];
        g_rowptr[i] = v;
        g_cursor[i] = v;
    }
    if (i == 0) g_rowptr[n] = e;
}

__global__ void k_fill(const void* eraw, int e) {
    int i = blockIdx.x * blockDim.x + threadIdx.x;
    if (i >= e) return;
    int s, d;
    if (g_flag64) {
        const long long* p = (const long long*)eraw;
        s = (int)p[i];
        d = (int)p[(size_t)e + i];
    } else {
        const int* p = (const int*)eraw;
        s = p[i];
        d = p[e + i];
    }
    int pos = atomicAdd(&g_cursor[d], 1);
    g_col[pos] = s;
}

// ---------------- dual GEMM: P = X @ Wrel ; B = X @ Wroot + b_rel ----------------
// 256 threads, 64-row tile; each thread: 4 rows x 8 cols via f32x2 packed FMA.
template <int K>
__global__ __launch_bounds__(256) void k_gemm_dual(
    const float* __restrict__ X,
    const float* __restrict__ Wrel,
    const float* __restrict__ Wroot,
    const float* __restrict__ brel,
    int n)
{
    extern __shared__ float sm[];
    float* Ws = sm;                // [K][128]: cols 0-63 = Wrel, 64-127 = Wroot
    float* Hs = sm + K * 128;      // [64][K]
    const float* src = (K == INCH) ? X : g_H;

    int tid = threadIdx.x;
    int row0 = blockIdx.x * 64;

    for (int i = tid; i < K * 64; i += 256) {
        int k = i >> 6, c = i & 63;
        Ws[k * 128 + c]      = Wrel[i];
        Ws[k * 128 + 64 + c] = Wroot[i];
    }
    for (int i = tid; i < (64 * K) / 4; i += 256) {
        int el = i * 4;
        int r = el / K, kk = el % K;
        int gr = row0 + r;
        float4 v = make_float4(0.f, 0.f, 0.f, 0.f);
        if (gr < n) v = *(const float4*)(src + (size_t)gr * K + kk);
        *(float4*)(Hs + r * K + kk) = v;
    }
    __syncthreads();

    int tx = tid & 15, ty = tid >> 4;
    int c0 = tx * 4;          // 4 contiguous cols in each half (conflict-free LDS.128)
    int r0 = ty * 4;

    // acc2[row][pair]: pair 0=(c0,c0+1)rel 1=(c0+2,c0+3)rel 2,3 = same in root half
    unsigned long long acc2[4][4];
#pragma unroll
    for (int i = 0; i < 4; i++)
#pragma unroll
        for (int j = 0; j < 4; j++) acc2[i][j] = 0ull;

#pragma unroll 8
    for (int k = 0; k < K; k++) {
        unsigned long long pa[4];
#pragma unroll
        for (int i = 0; i < 4; i++) {
            float a = Hs[(r0 + i) * K + k];
            pa[i] = pack2(a, a);
        }
        float4 b0 = *(float4*)&Ws[k * 128 + c0];        // Wrel cols
        float4 b1 = *(float4*)&Ws[k * 128 + 64 + c0];   // Wroot cols
        unsigned long long pb[4];
        pb[0] = pack2(b0.x, b0.y);
        pb[1] = pack2(b0.z, b0.w);
        pb[2] = pack2(b1.x, b1.y);
        pb[3] = pack2(b1.z, b1.w);
#pragma unroll
        for (int i = 0; i < 4; i++) {
            ffma2(acc2[i][0], pa[i], pb[0]);
            ffma2(acc2[i][1], pa[i], pb[1]);
            ffma2(acc2[i][2], pa[i], pb[2]);
            ffma2(acc2[i][3], pa[i], pb[3]);
        }
    }

    float bb0 = brel[c0 + 0], bb1 = brel[c0 + 1], bb2 = brel[c0 + 2], bb3 = brel[c0 + 3];
#pragma unroll
    for (int i = 0; i < 4; i++) {
        int gr = row0 + r0 + i;
        if (gr >= n) continue;
        float p0, p1, p2, p3, q0, q1, q2, q3;
        unpack2(acc2[i][0], p0, p1);
        unpack2(acc2[i][1], p2, p3);
        unpack2(acc2[i][2], q0, q1);
        unpack2(acc2[i][3], q2, q3);
        *(float4*)(g_P + (size_t)gr * 64 + c0) = make_float4(p0, p1, p2, p3);
        *(float4*)(g_B + (size_t)gr * 64 + c0) =
            make_float4(q0 + bb0, q1 + bb1, q2 + bb2, q3 + bb3);
    }
}

// ---------------- pull aggregation: H[i] = relu(B[i] + sum_{j in N(i)} P[j]) ----------------
// 16 threads per node, float4 per thread. P (25.6MB) is L2-resident.
__global__ __launch_bounds__(256) void k_agg(int n) {
    int t = blockIdx.x * blockDim.x + threadIdx.x;
    int gid = t >> 4;
    int l4 = (t & 15) * 4;
    if (gid >= n) return;
    int beg = g_rowptr[gid], end = g_rowptr[gid + 1];
    float4 acc = *(const float4*)(g_B + (size_t)gid * 64 + l4);
    int j = beg;
    for (; j + 3 < end; j += 4) {
        int s0 = g_col[j], s1 = g_col[j + 1], s2 = g_col[j + 2], s3 = g_col[j + 3];
        float4 v0 = *(const float4*)(g_P + (size_t)s0 * 64 + l4);
        float4 v1 = *(const float4*)(g_P + (size_t)s1 * 64 + l4);
        float4 v2 = *(const float4*)(g_P + (size_t)s2 * 64 + l4);
        float4 v3 = *(const float4*)(g_P + (size_t)s3 * 64 + l4);
        acc.x += (v0.x + v1.x) + (v2.x + v3.x);
        acc.y += (v0.y + v1.y) + (v2.y + v3.y);
        acc.z += (v0.z + v1.z) + (v2.z + v3.z);
        acc.w += (v0.w + v1.w) + (v2.w + v3.w);
    }
    for (; j < end; j++) {
        int s = g_col[j];
        float4 v = *(const float4*)(g_P + (size_t)s * 64 + l4);
        acc.x += v.x; acc.y += v.y; acc.z += v.z; acc.w += v.w;
    }
    acc.x = fmaxf(acc.x, 0.f);
    acc.y = fmaxf(acc.y, 0.f);
    acc.z = fmaxf(acc.z, 0.f);
    acc.w = fmaxf(acc.w, 0.f);
    *(float4*)(g_H + (size_t)gid * 64 + l4) = acc;
}

// ---------------- pooling: run-length accumulate (batch is sorted), few atomics ----------------
__global__ __launch_bounds__(256) void k_pool(int n) {
    int d = threadIdx.x & 63;
    int s = threadIdx.x >> 6;      // 0..3
    int start = blockIdx.x * 1024;
    int endn = min(start + 1024, n);
    float acc = 0.f;
    int curg = -1;
    for (int node = start + s; node < endn; node += 4) {
        int g = g_batch[node];
        if (g != curg) {
            if (curg >= 0) atomicAdd(&g_gsum[curg * 64 + d], acc);
            acc = 0.f; curg = g;
        }
        acc += g_H[(size_t)node * 64 + d];
    }
    if (curg >= 0) atomicAdd(&g_gsum[curg * 64 + d], acc);
}

__global__ void k_count(int n) {
    int g = threadIdx.x;           // 64 threads
    if (g >= 64) return;
    int lo0 = 0, hi = n;
    while (lo0 < hi) { int m = (lo0 + hi) >> 1; if (g_batch[m] < g) lo0 = m + 1; else hi = m; }
    int lo1 = lo0; hi = n;
    while (lo1 < hi) { int m = (lo1 + hi) >> 1; if (g_batch[m] < g + 1) lo1 = m + 1; else hi = m; }
    g_gcnt[g] = lo1 - lo0;
}

// ---------------- MLP head ----------------
__global__ __launch_bounds__(256) void k_head(
    const float* __restrict__ W1, const float* __restrict__ b1,
    const float* __restrict__ W2, const float* __restrict__ b2,
    float* __restrict__ out)
{
    __shared__ float pm[64 * 64];
    __shared__ float w1s[64 * 64];
    __shared__ float z[64 * 64];
    int tid = threadIdx.x;
    for (int i = tid; i < 4096; i += 256) {
        int g = i >> 6;
        pm[i] = g_gsum[i] / fmaxf((float)g_gcnt[g], 1.f);
        w1s[i] = W1[i];
    }
    __syncthreads();
    for (int idx = tid; idx < 4096; idx += 256) {
        int g = idx >> 6, jj = idx & 63;
        float s = b1[jj];
#pragma unroll 8
        for (int k = 0; k < 64; k++) s = fmaf(pm[g * 64 + k], w1s[k * 64 + jj], s);
        z[idx] = fmaxf(s, 0.f);
    }
    __syncthreads();
    if (tid < 128) {
        int g = tid >> 1, o = tid & 1;
        float s = b2[o];
#pragma unroll 8
        for (int jj = 0; jj < 64; jj++) s = fmaf(z[g * 64 + jj], W2[jj * 2 + o], s);
        out[g * 2 + o] = s;
    }
}

// ---------------- launch ----------------
extern "C" void kernel_launch(void* const* d_in, const int* in_sizes, int n_in,
                              void* d_out, int out_size)
{
    const float* x      = (const float*)d_in[0];
    const void*  eidx   = d_in[1];
    const void*  batch  = d_in[2];
    const float* wr0    = (const float*)d_in[3];
    const float* br0    = (const float*)d_in[4];
    const float* wroot0 = (const float*)d_in[5];
    const float* wr1    = (const float*)d_in[6];
    const float* br1    = (const float*)d_in[7];
    const float* wroot1 = (const float*)d_in[8];
    const float* wr2    = (const float*)d_in[9];
    const float* br2    = (const float*)d_in[10];
    const float* wroot2 = (const float*)d_in[11];
    const float* hw1    = (const float*)d_in[12];
    const float* hb1    = (const float*)d_in[13];
    const float* hw2    = (const float*)d_in[14];
    const float* hb2    = (const float*)d_in[15];

    int n = in_sizes[0] / INCH;    // 100000
    int e = in_sizes[1] / 2;       // 1600000 (element count is dtype-independent)

    cudaFuncSetAttribute(k_gemm_dual<INCH>, cudaFuncAttributeMaxDynamicSharedMemorySize,
                         INCH * 192 * 4);
    cudaFuncSetAttribute(k_gemm_dual<HID>, cudaFuncAttributeMaxDynamicSharedMemorySize,
                         HID * 192 * 4);

    k_detect<<<1, 256>>>((const int*)eidx);
    k_zero<<<(n + 255) / 256, 256>>>(n);
    k_hist<<<(e + 255) / 256, 256>>>(eidx, e);
    k_convert_batch<<<(n + 255) / 256, 256>>>(batch, n);

    int nb = (n + 1023) / 1024;
    k_scan1<<<nb, 1024>>>(n);
    k_scan2<<<1, 32>>>(nb);
    k_scan3<<<nb, 1024>>>(n, e);
    k_fill<<<(e + 255) / 256, 256>>>(eidx, e);

    int gb = (n + 63) / 64;
    int ab = ((n * 16) + 255) / 256;

    // Layer 0 (K=128 input)
    k_gemm_dual<INCH><<<gb, 256, INCH * 192 * 4>>>(x, wr0, wroot0, br0, n);
    k_agg<<<ab, 256>>>(n);
    // Layer 1
    k_gemm_dual<HID><<<gb, 256, HID * 192 * 4>>>(nullptr, wr1, wroot1, br1, n);
    k_agg<<<ab, 256>>>(n);
    // Layer 2
    k_gemm_dual<HID><<<gb, 256, HID * 192 * 4>>>(nullptr, wr2, wroot2, br2, n);
    k_agg<<<ab, 256>>>(n);

    k_pool<<<(n + 1023) / 1024, 256>>>(n);
    k_count<<<1, 64>>>(n);
    k_head<<<1, 256>>>(hw1, hb1, hw2, hb2, (float*)d_out);
}